// round 4
// baseline (speedup 1.0000x reference)
#include <cuda_runtime.h>

// Fixed problem shape
#define NMOL   256
#define NATOM  512
#define KNB    32
#define NTOT   (NMOL * NATOM)            // 131072 atoms
#define EDG    ((size_t)NTOT * KNB)      // 4194304 edges
#define TPB    128                       // 1 thread per atom
#define CAP    176                       // per-atom candidate cap (mean ~41, max ~150)
#define INF64  0xFFFFFFFFFFFFFFFFull

typedef unsigned long long u64;
typedef unsigned int       u32;

__device__ __forceinline__ u64 pk2(u32 lo, u32 hi) {
    u64 r; asm("mov.b64 %0, {%1, %2};" : "=l"(r) : "r"(lo), "r"(hi)); return r;
}
__device__ __forceinline__ void upk2(u64 v, u32& lo, u32& hi) {
    asm("mov.b64 {%0, %1}, %2;" : "=r"(lo), "=r"(hi) : "l"(v));
}
__device__ __forceinline__ u64 addx2(u64 a, u64 b) {
    u64 r; asm("add.rn.f32x2 %0, %1, %2;" : "=l"(r) : "l"(a), "l"(b)); return r;
}
__device__ __forceinline__ u64 mulx2(u64 a, u64 b) {
    u64 r; asm("mul.rn.f32x2 %0, %1, %2;" : "=l"(r) : "l"(a), "l"(b)); return r;
}

__global__ void __launch_bounds__(TPB, 7)
topo_kernel(const float* __restrict__ x, float* __restrict__ out)
{
    __shared__ __align__(16) float sx[NATOM];
    __shared__ __align__(16) float sy[NATOM];
    __shared__ __align__(16) float sz[NATOM];

    const int tid     = threadIdx.x;
    const int gatom   = blockIdx.x * TPB + tid;
    const int molbase = gatom & ~(NATOM - 1);
    const int i       = gatom & (NATOM - 1);

    // SoA molecule positions in shared memory
    for (int a = tid; a < NATOM; a += TPB) {
        const float* p = x + (size_t)(molbase + a) * 3;
        sx[a] = p[0]; sy[a] = p[1]; sz[a] = p[2];
    }
    __syncthreads();

    const float px = sx[i], py = sy[i], pz = sz[i];
    const u32 npxb = __float_as_uint(-px);
    const u32 npyb = __float_as_uint(-py);
    const u32 npzb = __float_as_uint(-pz);
    const u64 npx = pk2(npxb, npxb);
    const u64 npy = pk2(npyb, npyb);
    const u64 npz = pk2(npzb, npzb);

    const u64* sx2 = reinterpret_cast<const u64*>(sx);
    const u64* sy2 = reinterpret_cast<const u64*>(sy);
    const u64* sz2 = reinterpret_cast<const u64*>(sz);

    // ---- Phase 1: distances 2-at-a-time (f32x2, bit-exact RN), compact candidates ----
    // key = (d2bits << 9) | j : u64 order == (d2 asc, then j asc) == lax.top_k order.
    // accept 0 < d2 < 1  <=>  1 <= d2bits <= 0x3F7FFFFF  <=>  (d2bits - 1) < 0x3F7FFFFF
    u64 cand[CAP];
    int cnt = 0;

    #pragma unroll 4
    for (int t = 0; t < NATOM / 2; ++t) {
        const u64 jx = sx2[t], jy = sy2[t], jz = sz2[t];   // broadcast LDS (uniform t)
        const u64 dx = addx2(jx, npx);
        const u64 dy = addx2(jy, npy);
        const u64 dz = addx2(jz, npz);
        const u64 d2 = addx2(addx2(mulx2(dx, dx), mulx2(dy, dy)), mulx2(dz, dz));
        u32 b0, b1; upk2(d2, b0, b1);
        if (b0 - 1u < 0x3F7FFFFFu && cnt < CAP)
            cand[cnt++] = ((u64)b0 << 9) | (u32)(2 * t);
        if (b1 - 1u < 0x3F7FFFFFu && cnt < CAP)
            cand[cnt++] = ((u64)b1 << 9) | (u32)(2 * t + 1);
    }

    // ---- Phase 2: 32-entry max-heap of smallest keys (INF-prefilled) ----
    u64 h[33];
    h[32] = 0;                                   // pad child, never promoted (smallest)
    #pragma unroll
    for (int q = 0; q < 32; ++q) h[q] = INF64;
    u64 rootk = INF64;

    #pragma unroll 1
    for (int t = 0; t < cnt; ++t) {
        const u64 k = cand[t];
        if (k < rootk) {
            int p = 0;
            u64 newroot = k;
            #pragma unroll 1
            for (int lvl = 0; lvl < 5; ++lvl) {
                const int l = 2 * p + 1;
                if (l > 31) break;
                const u64 cl = h[l], cr = h[l + 1];        // h[32]=0 pads l==31
                const int c  = (cr > cl) ? l + 1 : l;
                const u64 cv = (cr > cl) ? cr : cl;
                if (cv <= k) break;
                h[p] = cv;                                  // promote larger child
                if (lvl == 0) newroot = cv;
                p = c;
            }
            h[p] = k;
            rootk = newroot;
        }
    }

    // ---- Phase 2b: heapsort pops (descending) -> slots 31..0 ascending.
    //      Keep only j (10-bit, 512 = invalid sentinel), packed 2 per register. ----
    u32 jp[16];
    #pragma unroll
    for (int q = 0; q < 16; ++q) jp[q] = 0;

    #pragma unroll
    for (int r = 0; r < 32; ++r) {
        const u64  res   = h[0];
        const bool valid = res < (1ull << 40);              // real keys < 2^39
        const u32  jv    = valid ? (u32)(res & 511u) : 512u;
        const int  slot  = 31 - r;
        jp[slot >> 1] |= jv << ((slot & 1) * 16);

        const int s2 = 31 - r;                               // new heap size
        const u64 last = h[s2];
        int p = 0;
        #pragma unroll 1
        for (int lvl = 0; lvl < 5; ++lvl) {
            const int l = 2 * p + 1;
            if (l >= s2) break;
            const u64 cl = h[l];
            const u64 cr = (l + 1 < s2) ? h[l + 1] : 0;
            const int c  = (cr > cl) ? l + 1 : l;
            const u64 cv = (cr > cl) ? cr : cl;
            if (cv <= last) break;
            h[p] = cv;
            p = c;
        }
        h[p] = last;
    }

    // ---- Phase 3: emit, per-atom contiguous -> all float4 stores ----
    float* obi  = out + (size_t)gatom * KNB;
    float* obj  = out + EDG + (size_t)gatom * KNB;
    float* ovec = out + 2 * EDG + (size_t)gatom * (3 * KNB);
    float* odst = out + 5 * EDG + (size_t)gatom * KNB;
    float* oval = out + 6 * EDG + (size_t)gatom * KNB;

    const float fgi = (float)gatom;

    #pragma unroll
    for (int qb = 0; qb < KNB / 4; ++qb) {
        float bi4[4], bj4[4], dd4[4], vv4[4], vec12[12];
        #pragma unroll
        for (int u = 0; u < 4; ++u) {
            const int  s  = qb * 4 + u;
            const u32  jv = (jp[s >> 1] >> ((s & 1) * 16)) & 0xFFFFu;
            const bool ok = (jv < NATOM);
            const int  j  = ok ? (int)jv : 0;
            // recompute d2 bit-identically (same inputs, same RN ops)
            const float dx = __fadd_rn(sx[j], -px);
            const float dy = __fadd_rn(sy[j], -py);
            const float dz = __fadd_rn(sz[j], -pz);
            const float d2 = __fadd_rn(__fadd_rn(__fmul_rn(dx, dx), __fmul_rn(dy, dy)),
                                       __fmul_rn(dz, dz));
            vec12[u * 3 + 0] = ok ? dx : 0.0f;
            vec12[u * 3 + 1] = ok ? dy : 0.0f;
            vec12[u * 3 + 2] = ok ? dz : 0.0f;
            bi4[u] = ok ? fgi : -1.0f;
            bj4[u] = ok ? (float)(molbase + j) : -1.0f;
            dd4[u] = ok ? __fsqrt_rn(d2) : 0.0f;
            vv4[u] = ok ? 1.0f : 0.0f;
        }
        *(float4*)(obi  + qb * 4)      = make_float4(bi4[0], bi4[1], bi4[2], bi4[3]);
        *(float4*)(obj  + qb * 4)      = make_float4(bj4[0], bj4[1], bj4[2], bj4[3]);
        *(float4*)(odst + qb * 4)      = make_float4(dd4[0], dd4[1], dd4[2], dd4[3]);
        *(float4*)(oval + qb * 4)      = make_float4(vv4[0], vv4[1], vv4[2], vv4[3]);
        *(float4*)(ovec + qb * 12 + 0) = make_float4(vec12[0], vec12[1], vec12[2],  vec12[3]);
        *(float4*)(ovec + qb * 12 + 4) = make_float4(vec12[4], vec12[5], vec12[6],  vec12[7]);
        *(float4*)(ovec + qb * 12 + 8) = make_float4(vec12[8], vec12[9], vec12[10], vec12[11]);
    }
}

extern "C" void kernel_launch(void* const* d_in, const int* in_sizes, int n_in,
                              void* d_out, int out_size)
{
    const float* x   = (const float*)d_in[0];
    float*       out = (float*)d_out;
    topo_kernel<<<NTOT / TPB, TPB>>>(x, out);
}

// round 6
// speedup vs baseline: 1.6923x; 1.6923x over previous
#include <cuda_runtime.h>

// Fixed problem shape
#define NMOL   256
#define NATOM  512
#define KNB    32
#define NTOT   (NMOL * NATOM)            // 131072 atoms
#define EDG    ((size_t)NTOT * KNB)      // 4194304 edges
#define TPB    128                       // 1 thread per atom
#define INF64  0xFFFFFFFFFFFFFFFFull

typedef unsigned long long u64;
typedef unsigned int       u32;

__device__ __forceinline__ u64 pk2(u32 lo, u32 hi) {
    u64 r; asm("mov.b64 %0, {%1, %2};" : "=l"(r) : "r"(lo), "r"(hi)); return r;
}
__device__ __forceinline__ void upk2(u64 v, u32& lo, u32& hi) {
    asm("mov.b64 {%0, %1}, %2;" : "=r"(lo), "=r"(hi) : "l"(v));
}
__device__ __forceinline__ u64 addx2(u64 a, u64 b) {
    u64 r; asm("add.rn.f32x2 %0, %1, %2;" : "=l"(r) : "l"(a), "l"(b)); return r;
}
__device__ __forceinline__ u64 mulx2(u64 a, u64 b) {
    u64 r; asm("mul.rn.f32x2 %0, %1, %2;" : "=l"(r) : "l"(a), "l"(b)); return r;
}

// Strided heap slot: bank = (2*tid)%32 independent of q -> divergent q conflict-free.
#define H(q) sh[(q) * TPB + tid]

__global__ void __launch_bounds__(TPB)
topo_kernel(const float* __restrict__ x, float* __restrict__ out)
{
    __shared__ __align__(16) float sx[NATOM];
    __shared__ __align__(16) float sy[NATOM];
    __shared__ __align__(16) float sz[NATOM];
    __shared__ u64 sh[33 * TPB];                     // 32 heap slots + pad slot 32

    const int tid     = threadIdx.x;
    const int gatom   = blockIdx.x * TPB + tid;
    const int molbase = gatom & ~(NATOM - 1);
    const int i       = gatom & (NATOM - 1);

    for (int a = tid; a < NATOM; a += TPB) {
        const float* p = x + (size_t)(molbase + a) * 3;
        sx[a] = p[0]; sy[a] = p[1]; sz[a] = p[2];
    }
    __syncthreads();

    const float px = sx[i], py = sy[i], pz = sz[i];
    const float nx = -px,   ny = -py,   nz = -pz;
    const u64 npx = pk2(__float_as_uint(nx), __float_as_uint(nx));
    const u64 npy = pk2(__float_as_uint(ny), __float_as_uint(ny));
    const u64 npz = pk2(__float_as_uint(nz), __float_as_uint(nz));

    const u64* sx2 = reinterpret_cast<const u64*>(sx);
    const u64* sy2 = reinterpret_cast<const u64*>(sy);
    const u64* sz2 = reinterpret_cast<const u64*>(sz);

    // ---- Phase 1: distances 2-at-a-time (bit-exact RN); accepts -> 512-bit mask.
    //      accept 0 < d2 < 1  <=>  (d2bits - 1) < 0x3F7FFFFF  (unsigned) ----
    u32 mloc[16];

    #pragma unroll 1
    for (int w = 0; w < 16; ++w) {
        u32 m = 0;
        #pragma unroll
        for (int s = 0; s < 16; ++s) {
            const int t  = w * 16 + s;
            const u64 dx = addx2(sx2[t], npx);
            const u64 dy = addx2(sy2[t], npy);
            const u64 dz = addx2(sz2[t], npz);
            const u64 d2 = addx2(addx2(mulx2(dx, dx), mulx2(dy, dy)), mulx2(dz, dz));
            u32 b0, b1; upk2(d2, b0, b1);
            if (b0 - 1u < 0x3F7FFFFFu) m |= (1u << (2 * s));
            if (b1 - 1u < 0x3F7FFFFFu) m |= (2u << (2 * s));
        }
        mloc[w] = m;
    }

    // ---- Phase 2: stream accepts into a max-heap of true size hc (<=32).
    //      key = (d2bits << 9) | j : u64 order == (d2 asc, j asc) == lax.top_k. ----
    #pragma unroll
    for (int q = 0; q < 32; ++q) H(q) = INF64;       // slots >= hc stay INF64 = invalid
    H(32) = 0;                                        // pad child for full-heap sift-down

    int hc    = 0;
    u64 rootk = INF64;

    #pragma unroll 1
    for (int w = 0; w < 16; ++w) {
        u32 m = mloc[w];
        while (m) {
            const int b = __ffs(m) - 1;
            m &= m - 1;
            const int j = (w << 5) + b;
            const float dx = __fadd_rn(sx[j], nx);   // bit-exact recompute
            const float dy = __fadd_rn(sy[j], ny);
            const float dz = __fadd_rn(sz[j], nz);
            const float d2 = __fadd_rn(__fadd_rn(__fmul_rn(dx, dx), __fmul_rn(dy, dy)),
                                       __fmul_rn(dz, dz));
            const u64 key = ((u64)__float_as_uint(d2) << 9) | (u32)j;

            if (hc < 32) {                            // grow: sift-up (heap size = hc)
                int p = hc++;
                while (p) {
                    const int par = (p - 1) >> 1;
                    const u64 pv  = H(par);
                    if (pv >= key) break;
                    H(p) = pv;
                    p = par;
                }
                H(p) = key;
                if (p == 0) rootk = key;
            } else if (key < rootk) {                 // full: replace root, sift-down
                int p = 0;
                u64 newroot = key;
                #pragma unroll 1
                for (;;) {
                    const int l = 2 * p + 1;
                    if (l > 31) break;
                    const u64 cl = H(l), cr = H(l + 1);   // H(32)=0 pads l==31
                    const int c  = (cr > cl) ? l + 1 : l;
                    const u64 cv = (cr > cl) ? cr : cl;
                    if (cv <= key) break;
                    H(p) = cv;
                    if (p == 0) newroot = cv;
                    p = c;
                }
                H(p) = key;
                rootk = newroot;
            }
        }
    }

    // ---- Phase 2b: in-place heapsort over the TRUE size hc.
    //      Popped max goes to freed slot H(size) -> H(0..hc-1) ascending. ----
    int size = hc;
    #pragma unroll 1
    while (size > 0) {
        const u64 res = H(0);
        --size;
        const u64 last = H(size);
        H(size) = res;
        int p = 0;
        #pragma unroll 1
        for (;;) {
            const int l = 2 * p + 1;
            if (l >= size) break;
            const u64 cl = H(l);
            const u64 cr = (l + 1 < size) ? H(l + 1) : 0;
            const int c  = (cr > cl) ? l + 1 : l;
            const u64 cv = (cr > cl) ? cr : cl;
            if (cv <= last) break;
            H(p) = cv;
            p = c;
        }
        H(p) = last;
    }

    // ---- Phase 3: emit, per-atom contiguous -> all float4 stores.
    //      H(s) gives both j and d2bits; INF64 slots are invalid. ----
    float* obi  = out + (size_t)gatom * KNB;
    float* obj  = out + EDG + (size_t)gatom * KNB;
    float* ovec = out + 2 * EDG + (size_t)gatom * (3 * KNB);
    float* odst = out + 5 * EDG + (size_t)gatom * KNB;
    float* oval = out + 6 * EDG + (size_t)gatom * KNB;

    const float fgi = (float)gatom;

    #pragma unroll
    for (int qb = 0; qb < KNB / 4; ++qb) {
        float bi4[4], bj4[4], dd4[4], vv4[4], vec12[12];
        #pragma unroll
        for (int u = 0; u < 4; ++u) {
            const int  s   = qb * 4 + u;
            const u64  key = H(s);
            const bool ok  = key < (1ull << 40);      // real keys < 2^39
            const int  j   = (int)(key & 511u);       // 511 for invalid: safe index
            const u32  d2b = (u32)(key >> 9);
            const float dx = __fadd_rn(sx[j], nx);
            const float dy = __fadd_rn(sy[j], ny);
            const float dz = __fadd_rn(sz[j], nz);
            vec12[u * 3 + 0] = ok ? dx : 0.0f;
            vec12[u * 3 + 1] = ok ? dy : 0.0f;
            vec12[u * 3 + 2] = ok ? dz : 0.0f;
            bi4[u] = ok ? fgi : -1.0f;
            bj4[u] = ok ? (float)(molbase + j) : -1.0f;
            dd4[u] = ok ? __fsqrt_rn(__uint_as_float(d2b)) : 0.0f;
            vv4[u] = ok ? 1.0f : 0.0f;
        }
        *(float4*)(obi  + qb * 4)      = make_float4(bi4[0], bi4[1], bi4[2], bi4[3]);
        *(float4*)(obj  + qb * 4)      = make_float4(bj4[0], bj4[1], bj4[2], bj4[3]);
        *(float4*)(odst + qb * 4)      = make_float4(dd4[0], dd4[1], dd4[2], dd4[3]);
        *(float4*)(oval + qb * 4)      = make_float4(vv4[0], vv4[1], vv4[2], vv4[3]);
        *(float4*)(ovec + qb * 12 + 0) = make_float4(vec12[0], vec12[1], vec12[2],  vec12[3]);
        *(float4*)(ovec + qb * 12 + 4) = make_float4(vec12[4], vec12[5], vec12[6],  vec12[7]);
        *(float4*)(ovec + qb * 12 + 8) = make_float4(vec12[8], vec12[9], vec12[10], vec12[11]);
    }
}

extern "C" void kernel_launch(void* const* d_in, const int* in_sizes, int n_in,
                              void* d_out, int out_size)
{
    const float* x   = (const float*)d_in[0];
    float*       out = (float*)d_out;
    topo_kernel<<<NTOT / TPB, TPB>>>(x, out);
}

// round 7
// speedup vs baseline: 1.8900x; 1.1168x over previous
#include <cuda_runtime.h>

// Fixed problem shape
#define NMOL   256
#define NATOM  512
#define KNB    32
#define NTOT   (NMOL * NATOM)            // 131072 atoms
#define EDG    ((size_t)NTOT * KNB)      // 4194304 edges
#define TPB    128                       // 1 thread per atom
#define INF64  0xFFFFFFFFFFFFFFFFull
#define ACCB   0x3F7FFFFFu               // (b-1) < ACCB  <=>  0 < d2 < 1
#define LOB    0x3F199999u               // (b-1) < LOB   <=>  0 < d2 < 0.6f

typedef unsigned long long u64;
typedef unsigned int       u32;

__device__ __forceinline__ u64 pk2(u32 lo, u32 hi) {
    u64 r; asm("mov.b64 %0, {%1, %2};" : "=l"(r) : "r"(lo), "r"(hi)); return r;
}
__device__ __forceinline__ void upk2(u64 v, u32& lo, u32& hi) {
    asm("mov.b64 {%0, %1}, %2;" : "=r"(lo), "=r"(hi) : "l"(v));
}
__device__ __forceinline__ u64 addx2(u64 a, u64 b) {
    u64 r; asm("add.rn.f32x2 %0, %1, %2;" : "=l"(r) : "l"(a), "l"(b)); return r;
}
__device__ __forceinline__ u64 mulx2(u64 a, u64 b) {
    u64 r; asm("mul.rn.f32x2 %0, %1, %2;" : "=l"(r) : "l"(a), "l"(b)); return r;
}

// Strided heap slot: bank = (2*tid)%32 independent of q -> divergent q conflict-free.
#define H(q) sh[(q) * TPB + tid]

// 4-ary max-heap sift-down over fixed size 32 (slot 32 = pad 0, never wins).
// Returns the resulting root value (meaningful for p0 == 0 callers).
__device__ __forceinline__ u64 sift32(u64* sh, int tid, int p, u64 key)
{
    u64 newroot = key;
    #pragma unroll 1
    for (;;) {
        const int l = 4 * p + 1;
        if (l > 31) break;                        // p >= 8 -> leaf
        const u64 c0 = H(l);
        const u64 c1 = H(l + 1);
        const u64 c2 = H(l + 2);
        const u64 c3 = H(l + 3);                  // p==7 -> slot 32 pad (0)
        u64 m01, m23, mx; int i01, i23, im;
        if (c1 > c0) { m01 = c1; i01 = l + 1; } else { m01 = c0; i01 = l;     }
        if (c3 > c2) { m23 = c3; i23 = l + 3; } else { m23 = c2; i23 = l + 2; }
        if (m23 > m01) { mx = m23; im = i23; } else { mx = m01; im = i01; }
        if (mx <= key) break;
        H(p) = mx;
        if (p == 0) newroot = mx;
        p = im;
    }
    H(p) = key;
    return newroot;
}

// Stream one mask word through the full heap (replace-root when better).
__device__ __forceinline__ void stream_mask(
    u64* sh, int tid, u32 m, int w,
    const float* sx, const float* sy, const float* sz,
    float nx, float ny, float nz, u64& rootk)
{
    #pragma unroll 1
    while (m) {
        const int b = __ffs(m) - 1;
        m &= m - 1;
        const int j = (w << 5) + b;
        const float dx = __fadd_rn(sx[j], nx);    // bit-exact recompute
        const float dy = __fadd_rn(sy[j], ny);
        const float dz = __fadd_rn(sz[j], nz);
        const float d2 = __fadd_rn(__fadd_rn(__fmul_rn(dx, dx), __fmul_rn(dy, dy)),
                                   __fmul_rn(dz, dz));
        const u64 key = ((u64)__float_as_uint(d2) << 9) | (u32)j;
        if (key < rootk)
            rootk = sift32(sh, tid, 0, key);
    }
}

__global__ void __launch_bounds__(TPB)
topo_kernel(const float* __restrict__ x, float* __restrict__ out)
{
    __shared__ __align__(16) float sx[NATOM];
    __shared__ __align__(16) float sy[NATOM];
    __shared__ __align__(16) float sz[NATOM];
    __shared__ u64 sh[33 * TPB];                 // 32 heap slots + pad slot 32

    const int tid     = threadIdx.x;
    const int gatom   = blockIdx.x * TPB + tid;
    const int molbase = gatom & ~(NATOM - 1);
    const int i       = gatom & (NATOM - 1);

    for (int a = tid; a < NATOM; a += TPB) {
        const float* p = x + (size_t)(molbase + a) * 3;
        sx[a] = p[0]; sy[a] = p[1]; sz[a] = p[2];
    }
    __syncthreads();

    const float px = sx[i], py = sy[i], pz = sz[i];
    const float nx = -px,   ny = -py,   nz = -pz;
    const u64 npx = pk2(__float_as_uint(nx), __float_as_uint(nx));
    const u64 npy = pk2(__float_as_uint(ny), __float_as_uint(ny));
    const u64 npz = pk2(__float_as_uint(nz), __float_as_uint(nz));

    const u64* sx2 = reinterpret_cast<const u64*>(sx);
    const u64* sy2 = reinterpret_cast<const u64*>(sy);
    const u64* sz2 = reinterpret_cast<const u64*>(sz);

    // ---- Phase 1: distances 2-at-a-time (bit-exact RN); two 512-bit masks:
    //      macc = accept (0<d2<1), mlo = near subset (0<d2<0.6). ----
    u32 macc[16], mlo[16];

    #pragma unroll 1
    for (int w = 0; w < 16; ++w) {
        u32 ma = 0, ml = 0;
        #pragma unroll
        for (int s = 0; s < 16; ++s) {
            const int t  = w * 16 + s;
            const u64 dx = addx2(sx2[t], npx);
            const u64 dy = addx2(sy2[t], npy);
            const u64 dz = addx2(sz2[t], npz);
            const u64 d2 = addx2(addx2(mulx2(dx, dx), mulx2(dy, dy)), mulx2(dz, dz));
            u32 b0, b1; upk2(d2, b0, b1);
            if (b0 - 1u < ACCB) ma |= (1u << (2 * s));
            if (b1 - 1u < ACCB) ma |= (2u << (2 * s));
            if (b0 - 1u < LOB)  ml |= (1u << (2 * s));
            if (b1 - 1u < LOB)  ml |= (2u << (2 * s));
        }
        macc[w] = ma;
        mlo[w]  = ml;
    }

    // ---- Heap prefill (INF64 = invalid; lanes with <32 neighbors keep some) ----
    #pragma unroll
    for (int q = 0; q < 32; ++q) H(q) = INF64;
    H(32) = 0;                                    // pad child: never promoted

    // ---- Stage A: append-only fill, near candidates first, then far. ----
    int hc = 0;
    int wr = 16; u32 mr = 0;                      // mlo resume point
    int wh = 16; u32 mh = 0;                      // mhi resume point

    #pragma unroll 1
    for (int w = 0; w < 16; ++w) {
        u32 m = mlo[w];
        #pragma unroll 1
        while (m && hc < 32) {
            const int b = __ffs(m) - 1;
            m &= m - 1;
            const int j = (w << 5) + b;
            const float dx = __fadd_rn(sx[j], nx);
            const float dy = __fadd_rn(sy[j], ny);
            const float dz = __fadd_rn(sz[j], nz);
            const float d2 = __fadd_rn(__fadd_rn(__fmul_rn(dx, dx), __fmul_rn(dy, dy)),
                                       __fmul_rn(dz, dz));
            H(hc) = ((u64)__float_as_uint(d2) << 9) | (u32)j;
            ++hc;
        }
        if (m) { wr = w; mr = m; break; }         // filled with lo bits remaining
    }

    if (hc == 32) {
        if (wr < 16 || true) { wh = 0; mh = macc[0] ^ mlo[0]; }  // all of hi pending
    } else {
        #pragma unroll 1
        for (int w = 0; w < 16; ++w) {
            u32 m = macc[w] ^ mlo[w];
            #pragma unroll 1
            while (m && hc < 32) {
                const int b = __ffs(m) - 1;
                m &= m - 1;
                const int j = (w << 5) + b;
                const float dx = __fadd_rn(sx[j], nx);
                const float dy = __fadd_rn(sy[j], ny);
                const float dz = __fadd_rn(sz[j], nz);
                const float d2 = __fadd_rn(__fadd_rn(__fmul_rn(dx, dx), __fmul_rn(dy, dy)),
                                           __fmul_rn(dz, dz));
                H(hc) = ((u64)__float_as_uint(d2) << 9) | (u32)j;
                ++hc;
            }
            if (m) { wh = w; mh = m; break; }
        }
    }

    // ---- Floyd heapify: UNIFORM across the warp (8 sift-downs, 4-ary). ----
    #pragma unroll 1
    for (int p = 7; p >= 0; --p)
        sift32(sh, tid, p, H(p));
    u64 rootk = H(0);

    // ---- Stage B: stream remaining candidates (replace-root). Near first:
    //      heavy lanes then reject the entire far pass at ~4 inst/candidate. ----
    if (wr < 16) {
        stream_mask(sh, tid, mr, wr, sx, sy, sz, nx, ny, nz, rootk);
        #pragma unroll 1
        for (int w = wr + 1; w < 16; ++w)
            stream_mask(sh, tid, mlo[w], w, sx, sy, sz, nx, ny, nz, rootk);
    }
    if (wh < 16) {
        stream_mask(sh, tid, mh, wh, sx, sy, sz, nx, ny, nz, rootk);
        #pragma unroll 1
        for (int w = wh + 1; w < 16; ++w)
            stream_mask(sh, tid, macc[w] ^ mlo[w], w, sx, sy, sz, nx, ny, nz, rootk);
    }

    // ---- Heapsort: UNIFORM 31 pops (INF64s pop first into the tail slots),
    //      leaves H(0..31) ascending with INF64 invalid markers at the end. ----
    #pragma unroll 1
    for (int size = 31; size >= 1; --size) {
        const u64 top = H(0);
        u64 key = H(size);
        H(size) = top;
        int p = 0;
        #pragma unroll 1
        for (;;) {
            const int l = 4 * p + 1;
            if (l >= size) break;
            const u64 c0 = H(l);
            const u64 c1 = (l + 1 < size) ? H(l + 1) : 0;
            const u64 c2 = (l + 2 < size) ? H(l + 2) : 0;
            const u64 c3 = (l + 3 < size) ? H(l + 3) : 0;
            u64 m01, m23, mx; int i01, i23, im;
            if (c1 > c0) { m01 = c1; i01 = l + 1; } else { m01 = c0; i01 = l;     }
            if (c3 > c2) { m23 = c3; i23 = l + 3; } else { m23 = c2; i23 = l + 2; }
            if (m23 > m01) { mx = m23; im = i23; } else { mx = m01; im = i01; }
            if (mx <= key) break;
            H(p) = mx;
            p = im;
        }
        H(p) = key;
    }

    // ---- Phase 3: emit, per-atom contiguous -> all float4 stores. ----
    float* obi  = out + (size_t)gatom * KNB;
    float* obj  = out + EDG + (size_t)gatom * KNB;
    float* ovec = out + 2 * EDG + (size_t)gatom * (3 * KNB);
    float* odst = out + 5 * EDG + (size_t)gatom * KNB;
    float* oval = out + 6 * EDG + (size_t)gatom * KNB;

    const float fgi = (float)gatom;

    #pragma unroll
    for (int qb = 0; qb < KNB / 4; ++qb) {
        float bi4[4], bj4[4], dd4[4], vv4[4], vec12[12];
        #pragma unroll
        for (int u = 0; u < 4; ++u) {
            const int  s   = qb * 4 + u;
            const u64  key = H(s);
            const bool ok  = key < (1ull << 40);  // real keys < 2^39
            const int  j   = (int)(key & 511u);
            const u32  d2b = (u32)(key >> 9);
            const float dx = __fadd_rn(sx[j], nx);
            const float dy = __fadd_rn(sy[j], ny);
            const float dz = __fadd_rn(sz[j], nz);
            vec12[u * 3 + 0] = ok ? dx : 0.0f;
            vec12[u * 3 + 1] = ok ? dy : 0.0f;
            vec12[u * 3 + 2] = ok ? dz : 0.0f;
            bi4[u] = ok ? fgi : -1.0f;
            bj4[u] = ok ? (float)(molbase + j) : -1.0f;
            dd4[u] = ok ? __fsqrt_rn(__uint_as_float(d2b)) : 0.0f;
            vv4[u] = ok ? 1.0f : 0.0f;
        }
        *(float4*)(obi  + qb * 4)      = make_float4(bi4[0], bi4[1], bi4[2], bi4[3]);
        *(float4*)(obj  + qb * 4)      = make_float4(bj4[0], bj4[1], bj4[2], bj4[3]);
        *(float4*)(odst + qb * 4)      = make_float4(dd4[0], dd4[1], dd4[2], dd4[3]);
        *(float4*)(oval + qb * 4)      = make_float4(vv4[0], vv4[1], vv4[2], vv4[3]);
        *(float4*)(ovec + qb * 12 + 0) = make_float4(vec12[0], vec12[1], vec12[2],  vec12[3]);
        *(float4*)(ovec + qb * 12 + 4) = make_float4(vec12[4], vec12[5], vec12[6],  vec12[7]);
        *(float4*)(ovec + qb * 12 + 8) = make_float4(vec12[8], vec12[9], vec12[10], vec12[11]);
    }
}

extern "C" void kernel_launch(void* const* d_in, const int* in_sizes, int n_in,
                              void* d_out, int out_size)
{
    const float* x   = (const float*)d_in[0];
    float*       out = (float*)d_out;
    topo_kernel<<<NTOT / TPB, TPB>>>(x, out);
}

// round 8
// speedup vs baseline: 2.1465x; 1.1357x over previous
#include <cuda_runtime.h>

// Fixed problem shape
#define NMOL   256
#define NATOM  512
#define KNB    32
#define NTOT   (NMOL * NATOM)            // 131072 atoms
#define EDG    ((size_t)NTOT * KNB)      // 4194304 edges
#define TPB    256                       // 1 thread per atom
#define INF64  0xFFFFFFFFFFFFFFFFull
#define ACCB   0x3F7FFFFFu               // (b-1) < ACCB  <=>  0 < d2 < 1
#define LOB    0x3F199999u               // (b-1) < LOB   <=>  0 < d2 < 0.6f
#define HIKEYMIN (0x3F19999Aull << 9)    // smallest possible hi-candidate key

typedef unsigned long long u64;
typedef unsigned int       u32;

// smem: heap (33 strided u64 slots) + SoA positions
#define SMEM_BYTES (33 * TPB * 8 + NATOM * 12)

__device__ __forceinline__ u64 pk2(u32 lo, u32 hi) {
    u64 r; asm("mov.b64 %0, {%1, %2};" : "=l"(r) : "r"(lo), "r"(hi)); return r;
}
__device__ __forceinline__ void upk2(u64 v, u32& lo, u32& hi) {
    asm("mov.b64 {%0, %1}, %2;" : "=r"(lo), "=r"(hi) : "l"(v));
}
__device__ __forceinline__ u64 addx2(u64 a, u64 b) {
    u64 r; asm("add.rn.f32x2 %0, %1, %2;" : "=l"(r) : "l"(a), "l"(b)); return r;
}
__device__ __forceinline__ u64 mulx2(u64 a, u64 b) {
    u64 r; asm("mul.rn.f32x2 %0, %1, %2;" : "=l"(r) : "l"(a), "l"(b)); return r;
}

// Strided heap slot: bank = (2*tid)%32 independent of q -> divergent q conflict-free.
#define H(q) sh[(q) * TPB + tid]

// 4-ary max-heap sift-down, size fixed at 32 (slot 32 = pad 0, never wins).
// Depth is provably <= 3: fully unrolled, no loop overhead.
// Returns resulting root value (meaningful when p0 == 0).
__device__ __forceinline__ u64 siftd(u64* sh, int tid, int p, u64 key)
{
    u64 newroot = key;
    #pragma unroll
    for (int lvl = 0; lvl < 3; ++lvl) {
        const int l = 4 * p + 1;
        if (l > 31) break;                        // leaf
        const u64 c0 = H(l);
        const u64 c1 = H(l + 1);
        const u64 c2 = H(l + 2);
        const u64 c3 = H(l + 3);                  // p==7 -> slot 32 pad (0)
        u64 m01, m23, mx; int i01, i23, im;
        if (c1 > c0) { m01 = c1; i01 = l + 1; } else { m01 = c0; i01 = l;     }
        if (c3 > c2) { m23 = c3; i23 = l + 3; } else { m23 = c2; i23 = l + 2; }
        if (m23 > m01) { mx = m23; im = i23; } else { mx = m01; im = i01; }
        if (mx <= key) break;
        H(p) = mx;
        if (p == 0) newroot = mx;
        p = im;
    }
    H(p) = key;
    return newroot;
}

// Stream one u64 mask word through the full heap (replace-root when better).
__device__ __forceinline__ void stream_word(
    u64* sh, int tid, u64 m, int w,
    const float* sx, const float* sy, const float* sz,
    float nx, float ny, float nz, u64& rootk)
{
    #pragma unroll 1
    while (m) {
        const int b = __ffsll(m) - 1;
        m &= m - 1;
        const int j = (w << 6) + b;
        const float dx = __fadd_rn(sx[j], nx);    // bit-exact recompute
        const float dy = __fadd_rn(sy[j], ny);
        const float dz = __fadd_rn(sz[j], nz);
        const float d2 = __fadd_rn(__fadd_rn(__fmul_rn(dx, dx), __fmul_rn(dy, dy)),
                                   __fmul_rn(dz, dz));
        const u64 key = ((u64)__float_as_uint(d2) << 9) | (u32)j;
        if (key < rootk)
            rootk = siftd(sh, tid, 0, key);
    }
}

__global__ void __launch_bounds__(TPB)
topo_kernel(const float* __restrict__ x, float* __restrict__ out)
{
    extern __shared__ char dsm[];
    u64*   sh = (u64*)dsm;                        // 33*TPB strided heap slots
    float* sx = (float*)(dsm + 33 * TPB * 8);
    float* sy = sx + NATOM;
    float* sz = sy + NATOM;

    const int tid     = threadIdx.x;
    const int gatom   = blockIdx.x * TPB + tid;
    const int molbase = gatom & ~(NATOM - 1);
    const int i       = gatom & (NATOM - 1);

    for (int a = tid; a < NATOM; a += TPB) {
        const float* p = x + (size_t)(molbase + a) * 3;
        sx[a] = p[0]; sy[a] = p[1]; sz[a] = p[2];
    }
    __syncthreads();

    const float px = sx[i], py = sy[i], pz = sz[i];
    const float nx = -px,   ny = -py,   nz = -pz;
    const u64 npx = pk2(__float_as_uint(nx), __float_as_uint(nx));
    const u64 npy = pk2(__float_as_uint(ny), __float_as_uint(ny));
    const u64 npz = pk2(__float_as_uint(nz), __float_as_uint(nz));

    const u64* sx2 = reinterpret_cast<const u64*>(sx);
    const u64* sy2 = reinterpret_cast<const u64*>(sy);
    const u64* sz2 = reinterpret_cast<const u64*>(sz);

    // ---- Phase 1: distances 2-at-a-time (bit-exact RN). u64 masks:
    //      mlo = near accepts (0<d2<0.6), mhi = far accepts (0.6<=d2<1). ----
    u64 mlo8[8], mhi8[8];

    #pragma unroll 1
    for (int w = 0; w < 8; ++w) {
        u64 ma = 0, ml = 0;
        #pragma unroll
        for (int s = 0; s < 32; ++s) {
            const int t  = w * 32 + s;
            const u64 dx = addx2(sx2[t], npx);
            const u64 dy = addx2(sy2[t], npy);
            const u64 dz = addx2(sz2[t], npz);
            const u64 d2 = addx2(addx2(mulx2(dx, dx), mulx2(dy, dy)), mulx2(dz, dz));
            u32 b0, b1; upk2(d2, b0, b1);
            if (b0 - 1u < ACCB) ma |= (1ull << (2 * s));
            if (b1 - 1u < ACCB) ma |= (2ull << (2 * s));
            if (b0 - 1u < LOB)  ml |= (1ull << (2 * s));
            if (b1 - 1u < LOB)  ml |= (2ull << (2 * s));
        }
        mhi8[w] = ma ^ ml;
        mlo8[w] = ml;
    }

    // ---- Heap prefill (INF64 = invalid; lanes with <32 neighbors keep some) ----
    #pragma unroll
    for (int q = 0; q < 32; ++q) H(q) = INF64;
    H(32) = 0;                                    // pad child: never promoted

    // ---- Stage A: append-only fill, near candidates first, then far. ----
    int hc = 0;
    int wr = 8; u64 mr = 0;                       // lo resume point
    int wh = 8; u64 mh = 0;                       // hi resume point

    #pragma unroll 1
    for (int w = 0; w < 8; ++w) {
        u64 m = mlo8[w];
        #pragma unroll 1
        while (m && hc < 32) {
            const int b = __ffsll(m) - 1;
            m &= m - 1;
            const int j = (w << 6) + b;
            const float dx = __fadd_rn(sx[j], nx);
            const float dy = __fadd_rn(sy[j], ny);
            const float dz = __fadd_rn(sz[j], nz);
            const float d2 = __fadd_rn(__fadd_rn(__fmul_rn(dx, dx), __fmul_rn(dy, dy)),
                                       __fmul_rn(dz, dz));
            H(hc) = ((u64)__float_as_uint(d2) << 9) | (u32)j;
            ++hc;
        }
        if (m) { wr = w; mr = m; break; }         // heap filled, lo bits remain
    }

    if (hc == 32) {
        wh = 0; mh = mhi8[0];                     // entire hi pass pending
    } else {
        #pragma unroll 1
        for (int w = 0; w < 8; ++w) {
            u64 m = mhi8[w];
            #pragma unroll 1
            while (m && hc < 32) {
                const int b = __ffsll(m) - 1;
                m &= m - 1;
                const int j = (w << 6) + b;
                const float dx = __fadd_rn(sx[j], nx);
                const float dy = __fadd_rn(sy[j], ny);
                const float dz = __fadd_rn(sz[j], nz);
                const float d2 = __fadd_rn(__fadd_rn(__fmul_rn(dx, dx), __fmul_rn(dy, dy)),
                                           __fmul_rn(dz, dz));
                H(hc) = ((u64)__float_as_uint(d2) << 9) | (u32)j;
                ++hc;
            }
            if (m) { wh = w; mh = m; break; }
        }
    }

    // ---- Floyd heapify: uniform 8 sift-downs (4-ary, depth <= 3) ----
    u64 rootk = INF64;
    #pragma unroll 1
    for (int p = 7; p >= 0; --p)
        rootk = siftd(sh, tid, p, H(p));          // p==0 call yields true root

    // ---- Stage B: stream remainders. Near first; far pass is skipped
    //      algebraically once rootk <= HIKEYMIN (no far key can enter). ----
    if (wr < 8) {
        stream_word(sh, tid, mr, wr, sx, sy, sz, nx, ny, nz, rootk);
        #pragma unroll 1
        for (int w = wr + 1; w < 8; ++w)
            stream_word(sh, tid, mlo8[w], w, sx, sy, sz, nx, ny, nz, rootk);
    }
    if (wh < 8) {
        u64 m0 = (rootk <= HIKEYMIN) ? 0ull : mh;
        stream_word(sh, tid, m0, wh, sx, sy, sz, nx, ny, nz, rootk);
        #pragma unroll 1
        for (int w = wh + 1; w < 8; ++w) {
            u64 m = (rootk <= HIKEYMIN) ? 0ull : mhi8[w];
            stream_word(sh, tid, m, w, sx, sy, sz, nx, ny, nz, rootk);
        }
    }

    // ---- Heapsort: 31 uniform pops (INF64s land in the tail slots),
    //      leaves H(0..31) ascending; sift unrolled (depth <= 3). ----
    #pragma unroll 1
    for (int size = 31; size >= 1; --size) {
        const u64 top = H(0);
        u64 key = H(size);
        H(size) = top;
        int p = 0;
        #pragma unroll
        for (int lvl = 0; lvl < 3; ++lvl) {
            const int l = 4 * p + 1;
            if (l >= size) break;
            const u64 c0 = H(l);
            const u64 c1 = (l + 1 < size) ? H(l + 1) : 0;
            const u64 c2 = (l + 2 < size) ? H(l + 2) : 0;
            const u64 c3 = (l + 3 < size) ? H(l + 3) : 0;
            u64 m01, m23, mx; int i01, i23, im;
            if (c1 > c0) { m01 = c1; i01 = l + 1; } else { m01 = c0; i01 = l;     }
            if (c3 > c2) { m23 = c3; i23 = l + 3; } else { m23 = c2; i23 = l + 2; }
            if (m23 > m01) { mx = m23; im = i23; } else { mx = m01; im = i01; }
            if (mx <= key) break;
            H(p) = mx;
            p = im;
        }
        H(p) = key;
    }

    // ---- Phase 3: emit, per-atom contiguous -> all float4 stores. ----
    float* obi  = out + (size_t)gatom * KNB;
    float* obj  = out + EDG + (size_t)gatom * KNB;
    float* ovec = out + 2 * EDG + (size_t)gatom * (3 * KNB);
    float* odst = out + 5 * EDG + (size_t)gatom * KNB;
    float* oval = out + 6 * EDG + (size_t)gatom * KNB;

    const float fgi = (float)gatom;

    #pragma unroll
    for (int qb = 0; qb < KNB / 4; ++qb) {
        float bi4[4], bj4[4], dd4[4], vv4[4], vec12[12];
        #pragma unroll
        for (int u = 0; u < 4; ++u) {
            const int  s   = qb * 4 + u;
            const u64  key = H(s);
            const bool ok  = key < (1ull << 40);  // real keys < 2^39
            const int  j   = (int)(key & 511u);
            const u32  d2b = (u32)(key >> 9);
            const float dx = __fadd_rn(sx[j], nx);
            const float dy = __fadd_rn(sy[j], ny);
            const float dz = __fadd_rn(sz[j], nz);
            vec12[u * 3 + 0] = ok ? dx : 0.0f;
            vec12[u * 3 + 1] = ok ? dy : 0.0f;
            vec12[u * 3 + 2] = ok ? dz : 0.0f;
            bi4[u] = ok ? fgi : -1.0f;
            bj4[u] = ok ? (float)(molbase + j) : -1.0f;
            dd4[u] = ok ? __fsqrt_rn(__uint_as_float(d2b)) : 0.0f;
            vv4[u] = ok ? 1.0f : 0.0f;
        }
        *(float4*)(obi  + qb * 4)      = make_float4(bi4[0], bi4[1], bi4[2], bi4[3]);
        *(float4*)(obj  + qb * 4)      = make_float4(bj4[0], bj4[1], bj4[2], bj4[3]);
        *(float4*)(odst + qb * 4)      = make_float4(dd4[0], dd4[1], dd4[2], dd4[3]);
        *(float4*)(oval + qb * 4)      = make_float4(vv4[0], vv4[1], vv4[2], vv4[3]);
        *(float4*)(ovec + qb * 12 + 0) = make_float4(vec12[0], vec12[1], vec12[2],  vec12[3]);
        *(float4*)(ovec + qb * 12 + 4) = make_float4(vec12[4], vec12[5], vec12[6],  vec12[7]);
        *(float4*)(ovec + qb * 12 + 8) = make_float4(vec12[8], vec12[9], vec12[10], vec12[11]);
    }
}

extern "C" void kernel_launch(void* const* d_in, const int* in_sizes, int n_in,
                              void* d_out, int out_size)
{
    const float* x   = (const float*)d_in[0];
    float*       out = (float*)d_out;

    cudaFuncSetAttribute(topo_kernel, cudaFuncAttributeMaxDynamicSharedMemorySize,
                         SMEM_BYTES);
    topo_kernel<<<NTOT / TPB, TPB, SMEM_BYTES>>>(x, out);
}